// round 1
// baseline (speedup 1.0000x reference)
#include <cuda_runtime.h>
#include <math.h>

#define KC 16
#define DD 32
#define NPAIR 528              // D*(D+1)/2
#define TILE 256
#define LOG2PIF 1.8378770664093453f
#define REGC 1e-6f
#define RESP_EPSF 1.1920928955078125e-6f   // 10 * eps(float32)

// ---------------- device state (no allocations allowed) ----------------
__device__ float g_w[KC];
__device__ float g_means[KC][DD];
__device__ float g_cov[KC][DD][DD];
__device__ __align__(16) float g_cf[NPAIR][KC];   // quad coefs: -0.5*P_ii diag, -P_ij offdiag (k contiguous)
__device__ __align__(16) float g_lin[DD][KC];     // b = P*mu  (d-major, k contiguous)
__device__ float g_cst[KC];                       // logw - logdet - 0.5*mu^T P mu - 0.5*D*log(2pi)
__device__ float g_nk[KC];
__device__ float g_sumx[KC][DD];
__device__ float g_S[KC][DD][DD];

// ---------------- init: copy inputs into working state ----------------
__global__ void init_k(const float* __restrict__ w, const float* __restrict__ m,
                       const float* __restrict__ c) {
    int tid = blockIdx.x * blockDim.x + threadIdx.x;
    int tot = gridDim.x * blockDim.x;
    for (int i = tid; i < KC * DD * DD; i += tot) ((float*)g_cov)[i] = c[i];
    for (int i = tid; i < KC * DD; i += tot) ((float*)g_means)[i] = m[i];
    if (tid == 0) {
        float s = 0.f;
        for (int k = 0; k < KC; k++) s += w[k];
        for (int k = 0; k < KC; k++) g_w[k] = w[k] / s;
    }
}

// ---------------- prep: per-component Cholesky -> precision coefs ----------------
// 16 blocks (one component each), 32 threads. Also zeroes the M accumulators.
__global__ void prep_k() {
    __shared__ float A[DD][DD + 1];
    int k = blockIdx.x;
    int lane = threadIdx.x;

    // zero accumulators for this component
    for (int i = lane; i < DD * DD; i += 32) ((float*)g_S[k])[i] = 0.f;
    if (lane < DD) g_sumx[k][lane] = 0.f;
    if (lane == 0) g_nk[k] = 0.f;

    // load covariance + REG*I
    for (int i = lane; i < DD * DD; i += 32) {
        int r = i >> 5, c = i & 31;
        A[r][c] = g_cov[k][r][c] + (r == c ? REGC : 0.f);
    }
    __syncwarp();

    // Cholesky (lower), lane = row
    for (int j = 0; j < DD; j++) {
        float ljj = sqrtf(A[j][j]);
        __syncwarp();
        if (lane == j) A[j][j] = ljj;
        else if (lane > j) A[lane][j] = A[lane][j] / ljj;
        __syncwarp();
        if (lane > j) {
            float lij = A[lane][j];
            for (int c2 = j + 1; c2 <= lane; c2++) A[lane][c2] -= lij * A[c2][j];
        }
        __syncwarp();
    }

    float logdet = 0.f;                       // = 0.5*log|Sigma|
    for (int j = 0; j < DD; j++) logdet += logf(A[j][j]);

    // P = L^{-T} L^{-1}; lane computes column `lane` of P via two triangular solves
    float y[DD];
#pragma unroll
    for (int r = 0; r < DD; r++) y[r] = (r == lane) ? 1.f : 0.f;
    // forward: L y = e_c
#pragma unroll
    for (int j = 0; j < DD; j++) {
        y[j] = y[j] / A[j][j];
#pragma unroll
        for (int i2 = j + 1; i2 < DD; i2++) y[i2] -= A[i2][j] * y[j];
    }
    // backward: L^T p = y
#pragma unroll
    for (int j = DD - 1; j >= 0; j--) {
        y[j] = y[j] / A[j][j];
#pragma unroll
        for (int i2 = 0; i2 < j; i2++) y[i2] -= A[j][i2] * y[j];
    }
    __syncwarp();
    // overwrite A with P (A[r][lane] = P[r][lane])
#pragma unroll
    for (int r = 0; r < DD; r++) A[r][lane] = y[r];
    __syncwarp();

    // pack quadratic coefs with -0.5 folded in: lp += cf * x_i * x_j (i<=j)
    for (int r = 0; r <= lane; r++) {
        int idx = r * DD - (r * (r - 1)) / 2 + (lane - r);
        g_cf[idx][k] = (r == lane ? -0.5f : -1.0f) * A[r][lane];
    }
    // b = P * mu
    float b = 0.f;
    for (int j = 0; j < DD; j++) b += A[lane][j] * g_means[k][j];
    g_lin[lane][k] = b;
    // c = mu . b  (warp reduce)
    float cv = b * g_means[k][lane];
    for (int o = 16; o; o >>= 1) cv += __shfl_xor_sync(0xffffffff, cv, o);
    if (lane == 0)
        g_cst[k] = logf(g_w[k]) - logdet - 0.5f * cv - 0.5f * (float)DD * LOG2PIF;
}

// ---------------- fused E + M kernel ----------------
// mode 0: E-step (resp in smem) + M-step accumulation (atomics at end)
// mode 1: final log-likelihood written to out
__global__ void __launch_bounds__(TILE) em_k(const float* __restrict__ X,
                                             float* __restrict__ out,
                                             int N, int ntiles, int mode) {
    extern __shared__ float sm[];
    float* x2 = sm;                         // [TILE][36]
    float* rs = x2 + TILE * 36;             // [TILE][17]
    float* cf = rs + TILE * 17;             // [528][16]
    float* ln = cf + NPAIR * KC;            // [32][16]
    float* cs = ln + DD * KC;               // [16]

    int tid = threadIdx.x;

    // stage coefficients
    for (int i = tid; i < (NPAIR * KC) / 4; i += blockDim.x)
        ((float4*)cf)[i] = ((const float4*)g_cf)[i];
    for (int i = tid; i < (DD * KC) / 4; i += blockDim.x)
        ((float4*)ln)[i] = ((const float4*)g_lin)[i];
    if (tid < KC) cs[tid] = g_cst[tid];

    // M accumulators: thread owns component kk, rows i0 and i0+16 of S_k
    int kk = tid & 15;
    int i0 = tid >> 4;
    float aS0[DD], aS1[DD];
#pragma unroll
    for (int j = 0; j < DD; j++) { aS0[j] = 0.f; aS1[j] = 0.f; }
    float aX0 = 0.f, aX1 = 0.f, aN = 0.f;

    for (int tile = blockIdx.x; tile < ntiles; tile += gridDim.x) {
        int base = tile * TILE;
        int cnt = N - base; if (cnt > TILE) cnt = TILE;

        __syncthreads();   // previous M-phase done with x2/rs
        // load X tile (row-major, padded to 36 floats/row; zero tail)
        for (int e = tid; e < TILE * DD; e += blockDim.x) {
            int s = e >> 5, d = e & 31;
            x2[s * 36 + d] = (s < cnt) ? X[(base + s) * DD + d] : 0.f;
        }
        __syncthreads();

        // ---- E phase: thread t = one sample ----
        {
            int t = tid;
            float xr[DD];
#pragma unroll
            for (int j4 = 0; j4 < 8; j4++) {
                float4 v = *(const float4*)&x2[t * 36 + j4 * 4];
                xr[j4 * 4 + 0] = v.x; xr[j4 * 4 + 1] = v.y;
                xr[j4 * 4 + 2] = v.z; xr[j4 * 4 + 3] = v.w;
            }
            float lp[KC];
#pragma unroll
            for (int k = 0; k < KC; k++) lp[k] = cs[k];
            // linear term  b . x
#pragma unroll
            for (int d = 0; d < DD; d++) {
                float xv = xr[d];
#pragma unroll
                for (int k4 = 0; k4 < 4; k4++) {
                    float4 c4 = *(const float4*)&ln[d * KC + k4 * 4];
                    lp[k4 * 4 + 0] += c4.x * xv;
                    lp[k4 * 4 + 1] += c4.y * xv;
                    lp[k4 * 4 + 2] += c4.z * xv;
                    lp[k4 * 4 + 3] += c4.w * xv;
                }
            }
            // quadratic term  -0.5 * x^T P x  (packed upper triangle)
            int p = 0;
#pragma unroll
            for (int i = 0; i < DD; i++) {
                float xi = xr[i];
#pragma unroll
                for (int j = i; j < DD; j++) {
                    float xx = xi * xr[j];
#pragma unroll
                    for (int k4 = 0; k4 < 4; k4++) {
                        float4 c4 = *(const float4*)&cf[p * KC + k4 * 4];
                        lp[k4 * 4 + 0] += c4.x * xx;
                        lp[k4 * 4 + 1] += c4.y * xx;
                        lp[k4 * 4 + 2] += c4.z * xx;
                        lp[k4 * 4 + 3] += c4.w * xx;
                    }
                    p++;
                }
            }
            // logsumexp
            float mx = lp[0];
#pragma unroll
            for (int k = 1; k < KC; k++) mx = fmaxf(mx, lp[k]);
            float s = 0.f;
#pragma unroll
            for (int k = 0; k < KC; k++) { lp[k] = __expf(lp[k] - mx); s += lp[k]; }

            if (mode == 1) {
                if (t < cnt) out[base + t] = mx + __logf(s);
            } else {
                float inv = 1.f / s;
#pragma unroll
                for (int k = 0; k < KC; k++)
                    rs[t * 17 + k] = (t < cnt) ? lp[k] * inv : 0.f;
            }
        }

        // ---- M phase ----
        if (mode == 0) {
            __syncthreads();
#pragma unroll 1
            for (int t = 0; t < TILE; t++) {
                float r = rs[t * 17 + kk];
                float xi0 = x2[t * 36 + i0];
                float xi1 = x2[t * 36 + i0 + 16];
                float u0 = r * xi0, u1 = r * xi1;
                aX0 += u0; aX1 += u1;
                if (i0 == 0) aN += r;
#pragma unroll
                for (int j4 = 0; j4 < 8; j4++) {
                    float4 xj = *(const float4*)&x2[t * 36 + j4 * 4];
                    aS0[j4 * 4 + 0] += u0 * xj.x; aS0[j4 * 4 + 1] += u0 * xj.y;
                    aS0[j4 * 4 + 2] += u0 * xj.z; aS0[j4 * 4 + 3] += u0 * xj.w;
                    aS1[j4 * 4 + 0] += u1 * xj.x; aS1[j4 * 4 + 1] += u1 * xj.y;
                    aS1[j4 * 4 + 2] += u1 * xj.z; aS1[j4 * 4 + 3] += u1 * xj.w;
                }
            }
        }
    }

    if (mode == 0) {
#pragma unroll
        for (int j = 0; j < DD; j++) {
            atomicAdd(&g_S[kk][i0][j], aS0[j]);
            atomicAdd(&g_S[kk][i0 + 16][j], aS1[j]);
        }
        atomicAdd(&g_sumx[kk][i0], aX0);
        atomicAdd(&g_sumx[kk][i0 + 16], aX1);
        if (i0 == 0) atomicAdd(&g_nk[kk], aN);
    }
}

// ---------------- finalize M-step: new params ----------------
__global__ void fin_k(int N) {
    __shared__ float m[DD];
    __shared__ float nk_s;
    int k = blockIdx.x, tid = threadIdx.x;
    if (tid == 0) nk_s = g_nk[k] + RESP_EPSF;
    __syncthreads();
    float nk = nk_s;
    if (tid < DD) {
        float mm = g_sumx[k][tid] / nk;
        m[tid] = mm;
        g_means[k][tid] = mm;
    }
    if (tid == 0) g_w[k] = nk / (float)N;
    __syncthreads();
    for (int i = tid; i < DD * DD; i += blockDim.x) {
        int r = i >> 5, c = i & 31;
        g_cov[k][r][c] = ((float*)g_S[k])[i] / nk - m[r] * m[c] + (r == c ? REGC : 0.f);
    }
}

// ---------------- host launcher (graph-capturable, no allocations) ----------------
extern "C" void kernel_launch(void* const* d_in, const int* in_sizes, int n_in,
                              void* d_out, int out_size) {
    const float* X = (const float*)d_in[0];
    const float* w = (const float*)d_in[1];
    const float* m = (const float*)d_in[2];
    const float* c = (const float*)d_in[3];
    float* out = (float*)d_out;

    int N = in_sizes[0] / DD;
    int ntiles = (N + TILE - 1) / TILE;
    int smem = (TILE * 36 + TILE * 17 + NPAIR * KC + DD * KC + KC) * (int)sizeof(float);

    cudaFuncSetAttribute(em_k, cudaFuncAttributeMaxDynamicSharedMemorySize, smem);

    int nb = 148;
    if (nb > ntiles) nb = ntiles;

    init_k<<<34, 512>>>(w, m, c);
    for (int it = 0; it < 5; it++) {           // n_iter = 5 (fixed problem instance)
        prep_k<<<KC, 32>>>();
        em_k<<<nb, TILE, smem>>>(X, nullptr, N, ntiles, 0);
        fin_k<<<KC, 256>>>(N);
    }
    prep_k<<<KC, 32>>>();
    em_k<<<nb, TILE, smem>>>(X, out, N, ntiles, 1);
}